// round 5
// baseline (speedup 1.0000x reference)
#include <cuda_runtime.h>
#include <cuda_fp16.h>
#include <cstddef>
#include <cstdint>

#define VOCAB 100000
#define NB    16384
#define LSEQ  200
#define EMB   128
#define NCLS  1000

#define ROWS_PER_POOL 8
#define POOL_BLOCKS   (NB / ROWS_PER_POOL)        // 2048
#define MT_ROWS       64                          // gemm m-tile rows
#define N_MT          (NB / MT_ROWS)              // 256 m-tiles
#define POOL_PER_MT   (MT_ROWS / ROWS_PER_POOL)   // 8 pool blocks per m-tile
#define GEMM_NT       16                          // n-tiles of 64 (covers 1000)
#define GEMM_BLOCKS   (N_MT * GEMM_NT)            // 4096

// Scratch (alloc-free rule: __device__ globals).
__device__ __align__(16) __half g_table_h[(size_t)VOCAB * EMB];
__device__ __align__(16) __half g_w_h[(size_t)NCLS * EMB];
__device__ __align__(16) __half g_pooled_h[(size_t)NB * EMB];
__device__ int g_cnt[N_MT];   // per-m-tile pool completion counters

// ---------------------------------------------------------------------------
// Stage 0: convert table AND fc_w fp32 -> fp16, and zero the counters.
// ---------------------------------------------------------------------------
#define N_TBL4 ((size_t)VOCAB * EMB / 4)
#define N_W4   ((size_t)NCLS * EMB / 4)
#define N_ALL4 (N_TBL4 + N_W4)

__global__ __launch_bounds__(256) void convert_kernel(const float* __restrict__ t,
                                                      const float* __restrict__ W) {
    if (blockIdx.x == 0 && threadIdx.x < N_MT)
        g_cnt[threadIdx.x] = 0;

    const size_t base = (size_t)blockIdx.x * 1024 + threadIdx.x;
    float4 v[4];
    bool   ok[4];
    #pragma unroll
    for (int i = 0; i < 4; ++i) {
        const size_t idx = base + (size_t)i * 256;
        ok[i] = idx < N_ALL4;
        if (ok[i])
            v[i] = (idx < N_TBL4) ? reinterpret_cast<const float4*>(t)[idx]
                                  : reinterpret_cast<const float4*>(W)[idx - N_TBL4];
    }
    #pragma unroll
    for (int i = 0; i < 4; ++i) {
        if (!ok[i]) continue;
        const size_t idx = base + (size_t)i * 256;
        union { __half2 h[2]; uint2 u; } pk;
        pk.h[0] = __floats2half2_rn(v[i].x, v[i].y);
        pk.h[1] = __floats2half2_rn(v[i].z, v[i].w);
        if (idx < N_TBL4) reinterpret_cast<uint2*>(g_table_h)[idx] = pk.u;
        else              reinterpret_cast<uint2*>(g_w_h)[idx - N_TBL4] = pk.u;
    }
}

// ---------------------------------------------------------------------------
// Fused pool + GEMM kernel.
// Blocks [0, 2048): pool 8 batch rows each (warp per row), then release
//   their m-tile counter.
// Blocks [2048, 6144): 64x64 GEMM tile. Load B (independent of pool),
//   spin-wait for the tile's 8 pool blocks, load A, HMMA, fused-bias store.
// Pool blocks have lower bids -> dispatched first -> no deadlock.
// ---------------------------------------------------------------------------
__device__ __forceinline__ void hacc(float4& a, uint2 u) {
    const float2 f0 = __half22float2(*reinterpret_cast<__half2*>(&u.x));
    const float2 f1 = __half22float2(*reinterpret_cast<__half2*>(&u.y));
    a.x += f0.x; a.y += f0.y; a.z += f1.x; a.w += f1.y;
}

__device__ __forceinline__ void mma16816(float* d,
                                         uint32_t a0, uint32_t a1, uint32_t a2, uint32_t a3,
                                         uint32_t b0, uint32_t b1) {
    asm volatile(
        "mma.sync.aligned.m16n8k16.row.col.f32.f16.f16.f32 "
        "{%0,%1,%2,%3}, {%4,%5,%6,%7}, {%8,%9}, {%0,%1,%2,%3};\n"
        : "+f"(d[0]), "+f"(d[1]), "+f"(d[2]), "+f"(d[3])
        : "r"(a0), "r"(a1), "r"(a2), "r"(a3), "r"(b0), "r"(b1));
}

// smem half-index with 16B-chunk XOR swizzle (row = 128 halfs = 16 chunks).
__device__ __forceinline__ int swz(int row, int chunk) {
    return row * 128 + ((chunk ^ (row & 7)) << 3);
}

__global__ __launch_bounds__(256) void fused_kernel(const int* __restrict__ seq,
                                                    const float* __restrict__ bias,
                                                    float* __restrict__ out) {
    __shared__ union {
        int tok[ROWS_PER_POOL][LSEQ];                  // 6.4 KB (pool path)
        struct { __half A[64 * 128]; __half B[64 * 128]; } g;  // 32 KB (gemm path)
    } sm;

    const int bid = blockIdx.x;
    const int tid = threadIdx.x;

    if (bid < POOL_BLOCKS) {
        // ----------------------- POOL PATH -----------------------
        const int wid  = tid >> 5;
        const int lane = tid & 31;
        const int b0   = bid * ROWS_PER_POOL;

        for (int i = tid; i < ROWS_PER_POOL * LSEQ; i += 256)
            sm.tok[i / LSEQ][i % LSEQ] = seq[(size_t)b0 * LSEQ + i];
        __syncthreads();

        float4 acc[8];
        #pragma unroll
        for (int i = 0; i < 8; ++i) acc[i] = make_float4(0.f, 0.f, 0.f, 0.f);

        for (int l = 0; l < LSEQ; l += 8) {   // 200 % 8 == 0
            int   tok[8];
            uint2 v[8];
            #pragma unroll
            for (int i = 0; i < 8; ++i) tok[i] = sm.tok[wid][l + i];
            #pragma unroll
            for (int i = 0; i < 8; ++i)
                if (tok[i])
                    v[i] = reinterpret_cast<const uint2*>(
                               g_table_h + (size_t)tok[i] * EMB)[lane];
            #pragma unroll
            for (int i = 0; i < 8; ++i)
                if (tok[i]) hacc(acc[i], v[i]);
        }

        float4 r;
        r.x = ((acc[0].x + acc[1].x) + (acc[2].x + acc[3].x)) +
              ((acc[4].x + acc[5].x) + (acc[6].x + acc[7].x));
        r.y = ((acc[0].y + acc[1].y) + (acc[2].y + acc[3].y)) +
              ((acc[4].y + acc[5].y) + (acc[6].y + acc[7].y));
        r.z = ((acc[0].z + acc[1].z) + (acc[2].z + acc[3].z)) +
              ((acc[4].z + acc[5].z) + (acc[6].z + acc[7].z));
        r.w = ((acc[0].w + acc[1].w) + (acc[2].w + acc[3].w)) +
              ((acc[4].w + acc[5].w) + (acc[6].w + acc[7].w));

        union { __half2 h[2]; uint2 u; } pk;
        pk.h[0] = __floats2half2_rn(r.x, r.y);
        pk.h[1] = __floats2half2_rn(r.z, r.w);
        reinterpret_cast<uint2*>(g_pooled_h + (size_t)(b0 + wid) * EMB)[lane] = pk.u;

        // Release: make stores visible, then bump the tile counter.
        __threadfence();
        __syncthreads();
        if (tid == 0) atomicAdd(&g_cnt[bid / POOL_PER_MT], 1);
        return;
    }

    // ----------------------- GEMM PATH -----------------------
    const int gid  = bid - POOL_BLOCKS;
    const int mt   = gid / GEMM_NT;          // ascending with bid
    const int n0   = (gid % GEMM_NT) * 64;
    const int m0   = mt * MT_ROWS;
    const int lane = tid & 31;
    const int wid  = tid >> 5;
    const int wm   = wid >> 2;               // 0..1 (m, 32 rows each)
    const int wn   = wid & 3;                // 0..3 (n, 16 cols each)

    // Load B tile first — independent of pool progress.
    {
        const int r0 = tid >> 4;
        const int c  = tid & 15;
        #pragma unroll
        for (int it = 0; it < 4; ++it) {
            const int r = r0 + it * 16;
            uint4 v = make_uint4(0u, 0u, 0u, 0u);
            if (n0 + r < NCLS)
                v = reinterpret_cast<const uint4*>(g_w_h + (size_t)(n0 + r) * EMB)[c];
            *reinterpret_cast<uint4*>(&sm.g.B[swz(r, c)]) = v;
        }
    }

    // Acquire: wait for this m-tile's pool blocks.
    if (tid == 0) {
        while (atomicOr(&g_cnt[mt], 0) < POOL_PER_MT) __nanosleep(64);
        __threadfence();
    }
    __syncthreads();

    // Load A tile.
    {
        const int r0 = tid >> 4;
        const int c  = tid & 15;
        #pragma unroll
        for (int it = 0; it < 4; ++it) {
            const int r = r0 + it * 16;
            const uint4 v = reinterpret_cast<const uint4*>(
                g_pooled_h + (size_t)(m0 + r) * EMB)[c];
            *reinterpret_cast<uint4*>(&sm.g.A[swz(r, c)]) = v;
        }
    }
    __syncthreads();

    float acc[2][2][4] = {};
    const int lq = lane >> 2;
    const int lr = lane & 3;

    #pragma unroll
    for (int ks = 0; ks < 8; ++ks) {
        uint32_t a[2][4];
        #pragma unroll
        for (int mi = 0; mi < 2; ++mi) {
            const int r  = wm * 32 + mi * 16 + lq;
            const int o0 = ((2 * ks)     ^ (r & 7)) * 8 + lr * 2;
            const int o1 = ((2 * ks + 1) ^ (r & 7)) * 8 + lr * 2;
            a[mi][0] = *reinterpret_cast<const uint32_t*>(&sm.g.A[r * 128 + o0]);
            a[mi][1] = *reinterpret_cast<const uint32_t*>(&sm.g.A[(r + 8) * 128 + o0]);
            a[mi][2] = *reinterpret_cast<const uint32_t*>(&sm.g.A[r * 128 + o1]);
            a[mi][3] = *reinterpret_cast<const uint32_t*>(&sm.g.A[(r + 8) * 128 + o1]);
        }
        #pragma unroll
        for (int nt = 0; nt < 2; ++nt) {
            const int n  = wn * 16 + nt * 8 + lq;
            const int o0 = ((2 * ks)     ^ (n & 7)) * 8 + lr * 2;
            const int o1 = ((2 * ks + 1) ^ (n & 7)) * 8 + lr * 2;
            const uint32_t b0 = *reinterpret_cast<const uint32_t*>(&sm.g.B[n * 128 + o0]);
            const uint32_t b1 = *reinterpret_cast<const uint32_t*>(&sm.g.B[n * 128 + o1]);
            #pragma unroll
            for (int mi = 0; mi < 2; ++mi)
                mma16816(acc[mi][nt], a[mi][0], a[mi][1], a[mi][2], a[mi][3], b0, b1);
        }
    }

    // Epilogue: fused bias, predicated float2 stores.
    #pragma unroll
    for (int nt = 0; nt < 2; ++nt) {
        const int n = n0 + wn * 16 + nt * 8 + lr * 2;
        if (n < NCLS) {
            const float2 b2 = *reinterpret_cast<const float2*>(bias + n);
            #pragma unroll
            for (int mi = 0; mi < 2; ++mi) {
                const int m = m0 + wm * 32 + mi * 16 + lq;
                float2 r0, r1;
                r0.x = acc[mi][nt][0] + b2.x;
                r0.y = acc[mi][nt][1] + b2.y;
                r1.x = acc[mi][nt][2] + b2.x;
                r1.y = acc[mi][nt][3] + b2.y;
                *reinterpret_cast<float2*>(out + (size_t)m * NCLS + n)       = r0;
                *reinterpret_cast<float2*>(out + (size_t)(m + 8) * NCLS + n) = r1;
            }
        }
    }
}

extern "C" void kernel_launch(void* const* d_in, const int* in_sizes, int n_in,
                              void* d_out, int out_size) {
    const int*   seq   = (const int*)d_in[0];
    const float* table = (const float*)d_in[1];
    const float* W     = (const float*)d_in[2];
    const float* bias  = (const float*)d_in[3];
    float*       out   = (float*)d_out;

    const int conv_blocks = (int)((N_ALL4 + 1023) / 1024);
    convert_kernel<<<conv_blocks, 256>>>(table, W);

    fused_kernel<<<POOL_BLOCKS + GEMM_BLOCKS, 256>>>(seq, bias, out);
}